// round 13
// baseline (speedup 1.0000x reference)
#include <cuda_runtime.h>
#include <cstdint>

// Problem constants (fixed by the dataset)
#define LQ_   256
#define HH_   2
#define HQ_   32
#define DD_   128
#define SS_   16
#define BS_   64
#define GG_   16
#define NB_   64                           // Lkv / BS
#define SM_SCALE 0.08838834764831845f      // 1/sqrt(128)

// Packed KV scratch, tf32-pre-rounded (rna), float4 = two fragment pairs.
// kpack[h][nb][wrp:4][kt:16][p:4][ul:8] =
//   {K[wrp*16+ul][kt*8+p], ..[kt*8+p+4], K[wrp*16+8+ul][kt*8+p], ..[+4]}
// vpack[h][nb][wrp:4][kt:8][pair:2][p:4][dl:8] =   (d0 = wrp*32 + pair*16)
//   {V[kt*8+p][d0+dl], V[kt*8+p+4][d0+dl], V[kt*8+p][d0+8+dl], V[kt*8+p+4][d0+8+dl]}
__device__ float4 g_kpack[HH_ * NB_ * 2048];
__device__ float4 g_vpack[HH_ * NB_ * 2048];

// Shared memory (float offsets). Row pitches !≡ 0 mod 128B for ldmatrix.
#define QSH_OFF  0
#define QS_STR   132                       // 16 rows x 132 (rna(Q*scale))
#define PSH_OFF  (QSH_OFF + 16*132)        // 2112 ; double-buffered 2x16x68
#define PS_STR   68
#define WS_OFF   (PSH_OFF + 2*16*68)       // 4288
#define IDX_OFF  (WS_OFF + 256)            // 4544
#define SMEM_FLOATS (IDX_OFF + 16)
#define SMEM_BYTES  (SMEM_FLOATS * 4)      // 18,240 B

__device__ __forceinline__ unsigned smem_u32(const void* p) {
    return (unsigned)__cvta_generic_to_shared(p);
}

__device__ __forceinline__ void ldsm_x4(unsigned& r0, unsigned& r1,
                                        unsigned& r2, unsigned& r3, unsigned addr) {
    asm volatile("ldmatrix.sync.aligned.m8n8.x4.shared.b16 {%0,%1,%2,%3}, [%4];"
                 : "=r"(r0), "=r"(r1), "=r"(r2), "=r"(r3) : "r"(addr));
}

__device__ __forceinline__ void mma_tf32(float c[4],
                                         unsigned a0, unsigned a1, unsigned a2, unsigned a3,
                                         unsigned b0, unsigned b1) {
    asm volatile("mma.sync.aligned.m16n8k8.row.col.f32.tf32.tf32.f32 "
                 "{%0,%1,%2,%3}, {%4,%5,%6,%7}, {%8,%9}, {%0,%1,%2,%3};"
                 : "+f"(c[0]), "+f"(c[1]), "+f"(c[2]), "+f"(c[3])
                 : "r"(a0), "r"(a1), "r"(a2), "r"(a3), "r"(b0), "r"(b1));
}

__device__ __forceinline__ unsigned tf32_hi(unsigned x) {
    unsigned r;
    asm("cvt.rna.tf32.f32 %0, %1;" : "=r"(r) : "r"(x));
    return r;
}
__device__ __forceinline__ unsigned fu(float x) { return __float_as_uint(x); }
__device__ __forceinline__ float rna_f(float x) {
    return __uint_as_float(tf32_hi(__float_as_uint(x)));
}

// ---------------------------------------------------------------------------
// Prepass: pack K and V (tf32-rna) into paired-tile float4 layouts.
// ---------------------------------------------------------------------------
__global__ void __launch_bounds__(128)
pack_kv_kernel(const float* __restrict__ k, const float* __restrict__ v)
{
    const int nb = blockIdx.x, h = blockIdx.y;
    const float* kb = k + ((size_t)nb * BS_ * HH_ + h) * DD_;
    const float* vb = v + ((size_t)nb * BS_ * HH_ + h) * DD_;
    float4* kout = g_kpack + ((size_t)h * NB_ + nb) * 2048;
    float4* vout = g_vpack + ((size_t)h * NB_ + nb) * 2048;

    // K: pos = ((wrp*16 + kt)*4 + p)*8 + ul
    for (int pos = threadIdx.x; pos < 2048; pos += 128) {
        int ul = pos & 7, p = (pos >> 3) & 3, kt = (pos >> 5) & 15, wrp = pos >> 9;
        int u0 = wrp * 16 + ul, u1 = u0 + 8, d = kt * 8 + p;
        kout[pos] = make_float4(rna_f(kb[(size_t)u0 * (HH_ * DD_) + d]),
                                rna_f(kb[(size_t)u0 * (HH_ * DD_) + d + 4]),
                                rna_f(kb[(size_t)u1 * (HH_ * DD_) + d]),
                                rna_f(kb[(size_t)u1 * (HH_ * DD_) + d + 4]));
    }
    // V: pos = (((wrp*8 + kt)*2 + pair)*4 + p)*8 + dl
    for (int pos = threadIdx.x; pos < 2048; pos += 128) {
        int dl = pos & 7, p = (pos >> 3) & 3, pair = (pos >> 5) & 1;
        int kt = (pos >> 6) & 7, wrp = pos >> 9;
        int d0 = wrp * 32 + pair * 16 + dl, u = kt * 8 + p;
        vout[pos] = make_float4(rna_f(vb[(size_t)u * (HH_ * DD_) + d0]),
                                rna_f(vb[(size_t)(u + 4) * (HH_ * DD_) + d0]),
                                rna_f(vb[(size_t)u * (HH_ * DD_) + d0 + 8]),
                                rna_f(vb[(size_t)(u + 4) * (HH_ * DD_) + d0 + 8]));
    }
}

// ---------------------------------------------------------------------------
// Main kernel
// ---------------------------------------------------------------------------
__global__ void __launch_bounds__(128, 5)
hsa_prefill_kernel(const float* __restrict__ q, const float* __restrict__ w,
                   const int* __restrict__ bi, float* __restrict__ out)
{
    extern __shared__ float sm[];
    const int lq   = blockIdx.x;
    const int h    = blockIdx.y;
    const int tid  = threadIdx.x;
    const int warp = tid >> 5;
    const int lane = tid & 31;
    const int gID  = lane >> 2;   // 0..7
    const int tig  = lane & 3;    // 0..3

    // ---- Load Q tile [16][128]; store rna(Q * SM_SCALE).
    {
        const float* qb = q + ((size_t)lq * HQ_ + (size_t)h * GG_) * DD_;
        #pragma unroll
        for (int i = tid; i < (GG_ * DD_) / 4; i += 128) {
            int idx = i * 4;
            int g = idx >> 7, d = idx & 127;
            float4 val = *(const float4*)(qb + idx);
            *(uint4*)(sm + QSH_OFF + g * QS_STR + d) =
                make_uint4(tf32_hi(fu(val.x * SM_SCALE)),
                           tf32_hi(fu(val.y * SM_SCALE)),
                           tf32_hi(fu(val.z * SM_SCALE)),
                           tf32_hi(fu(val.w * SM_SCALE)));
        }
        const float* wb = w + ((size_t)lq * HQ_ + (size_t)h * GG_) * SS_;
        for (int i = tid; i < GG_ * SS_; i += 128) sm[WS_OFF + i] = wb[i];
        if (tid < SS_)
            ((int*)(sm + IDX_OFF))[tid] = bi[((size_t)lq * HH_ + h) * SS_ + tid];
    }
    __syncthreads();

    // Persistent O accumulators
    float oh[4][4];
    #pragma unroll
    for (int i = 0; i < 4; i++)
        #pragma unroll
        for (int j = 0; j < 4; j++) oh[i][j] = 0.f;

    // ldmatrix A-fragment address components
    const int lr = lane & 7;
    const int lt = lane >> 3;
    const int a_row = lr + ((lt & 1) << 3);
    const int a_col = (lt >> 1) << 2;

    // Per-lane packed-tile offsets (float4 units)
    const int lane_off = tig * 8 + gID;
    const float4* kp_base = g_kpack + (size_t)h * NB_ * 2048
                          + warp * 512 + lane_off;
    const float4* vp_base = g_vpack + (size_t)h * NB_ * 2048
                          + warp * 512 + lane_off;

    for (int s = 0; s < SS_; s++) {
        const int blk = ((const int*)(sm + IDX_OFF))[s];   // uniform across CTA
        float* psh = sm + PSH_OFF + (s & 1) * (16 * PS_STR);

        if (blk >= 0) {
            const float4* kp = kp_base + (size_t)blk * 2048;

            // ---- Scores S[16][64] = rna(Q*scale) @ K̃^T
            float cm[2][4] = {{0.f,0.f,0.f,0.f},{0.f,0.f,0.f,0.f}};
            #pragma unroll
            for (int kt = 0; kt < 16; kt++) {
                unsigned a0, a1, a2, a3;
                ldsm_x4(a0, a1, a2, a3,
                        smem_u32(sm + QSH_OFF + a_row * QS_STR + a_col + kt * 8));
                float4 kk = kp[kt * 32];   // both n-tiles in one LDG.128
                mma_tf32(cm[0], a0, a1, a2, a3, fu(kk.x), fu(kk.y));
                mma_tf32(cm[1], a0, a1, a2, a3, fu(kk.z), fu(kk.w));
            }
            // Spill scores (already scaled via Q) into PSH scratch
            #pragma unroll
            for (int nt = 0; nt < 2; nt++) {
                const int u = (warp * 2 + nt) * 8 + tig * 2;
                *(float2*)(psh + gID * PS_STR + u) =
                    make_float2(cm[nt][0], cm[nt][1]);
                *(float2*)(psh + (gID + 8) * PS_STR + u) =
                    make_float2(cm[nt][2], cm[nt][3]);
            }
            __syncthreads();

            // ---- Softmax over 64 keys; fold w[g][s]/sum; write rna(P).
            {
                const int g = tid >> 3, j = tid & 7;
                float vals[8];
                #pragma unroll
                for (int m = 0; m < 8; m++) vals[m] = psh[g * PS_STR + j + m * 8];
                float mx = vals[0];
                #pragma unroll
                for (int m = 1; m < 8; m++) mx = fmaxf(mx, vals[m]);
                mx = fmaxf(mx, __shfl_xor_sync(0xffffffffu, mx, 1));
                mx = fmaxf(mx, __shfl_xor_sync(0xffffffffu, mx, 2));
                mx = fmaxf(mx, __shfl_xor_sync(0xffffffffu, mx, 4));
                float sum = 0.f;
                #pragma unroll
                for (int m = 0; m < 8; m++) { vals[m] = __expf(vals[m] - mx); sum += vals[m]; }
                sum += __shfl_xor_sync(0xffffffffu, sum, 1);
                sum += __shfl_xor_sync(0xffffffffu, sum, 2);
                sum += __shfl_xor_sync(0xffffffffu, sum, 4);
                const float coef = sm[WS_OFF + g * SS_ + s] / sum;
                #pragma unroll
                for (int m = 0; m < 8; m++)
                    psh[g * PS_STR + j + m * 8] = rna_f(vals[m] * coef);
            }
            __syncthreads();

            // ---- O[16][128] += rna(P) @ Ṽ
            const float4* vp = vp_base + (size_t)blk * 2048;
            #pragma unroll
            for (int kt = 0; kt < 8; kt++) {
                unsigned a0, a1, a2, a3;
                ldsm_x4(a0, a1, a2, a3,
                        smem_u32(psh + a_row * PS_STR + a_col + kt * 8));
                float4 v01 = vp[kt * 64];        // d-tiles 0,1 for this warp
                float4 v23 = vp[kt * 64 + 32];   // d-tiles 2,3
                mma_tf32(oh[0], a0, a1, a2, a3, fu(v01.x), fu(v01.y));
                mma_tf32(oh[1], a0, a1, a2, a3, fu(v01.z), fu(v01.w));
                mma_tf32(oh[2], a0, a1, a2, a3, fu(v23.x), fu(v23.y));
                mma_tf32(oh[3], a0, a1, a2, a3, fu(v23.z), fu(v23.w));
            }
            // No end barrier: next iteration uses the OTHER P buffer.
        }
    }

    // ---- Write O: warp's d-slice, fragment rows gID / gID+8.
    float* ob = out + ((size_t)lq * HQ_ + (size_t)h * GG_) * DD_;
    #pragma unroll
    for (int nt = 0; nt < 4; nt++) {
        const int d = warp * 32 + nt * 8 + tig * 2;
        *(float2*)(ob + (size_t)gID * DD_ + d)       = make_float2(oh[nt][0], oh[nt][1]);
        *(float2*)(ob + (size_t)(gID + 8) * DD_ + d) = make_float2(oh[nt][2], oh[nt][3]);
    }
}

extern "C" void kernel_launch(void* const* d_in, const int* in_sizes, int n_in,
                              void* d_out, int out_size)
{
    const float* q  = (const float*)d_in[0];
    const float* k  = (const float*)d_in[1];
    const float* v  = (const float*)d_in[2];
    const float* w  = (const float*)d_in[3];
    const int*   bi = (const int*)d_in[4];
    float* out = (float*)d_out;

    pack_kv_kernel<<<dim3(NB_, HH_), 128>>>(k, v);

    cudaFuncSetAttribute(hsa_prefill_kernel,
                         cudaFuncAttributeMaxDynamicSharedMemorySize, SMEM_BYTES);
    hsa_prefill_kernel<<<dim3(LQ_, HH_), 128, SMEM_BYTES>>>(q, w, bi, out);
}

// round 14
// speedup vs baseline: 1.5237x; 1.5237x over previous
#include <cuda_runtime.h>
#include <cstdint>

// Problem constants (fixed by the dataset)
#define LQ_   256
#define HH_   2
#define HQ_   32
#define DD_   128
#define SS_   16
#define BS_   64
#define GG_   16
#define NB_   64                           // Lkv / BS
#define SM_SCALE 0.08838834764831845f      // 1/sqrt(128)

// Packed KV scratch: fragment-native float2 pairs, PRE-ROUNDED to tf32 (rna).
// kpack[h][nb][ub:8][kt:16][p:4][ul:8]  .x=rna(K[ub*8+ul][kt*8+p])  .y=.. p+4
// vpack[h][nb][db:16][kt:8][p:4][dl:8]  .x=rna(V[kt*8+p][db*8+dl])  .y=.. p+4
__device__ float2 g_kpack[HH_ * NB_ * 4096];
__device__ float2 g_vpack[HH_ * NB_ * 4096];

// Shared memory (float offsets). Row pitches !≡ 0 mod 128B for ldmatrix.
#define QSH_OFF  0
#define QS_STR   132                       // 16 rows x 132 (rna(Q*scale))
#define PSH_OFF  (QSH_OFF + 16*132)        // 2112 ; double-buffered 2x16x68
#define PS_STR   68
#define WS_OFF   (PSH_OFF + 2*16*68)       // 4288
#define IDX_OFF  (WS_OFF + 256)            // 4544
#define SMEM_FLOATS (IDX_OFF + 16)
#define SMEM_BYTES  (SMEM_FLOATS * 4)      // 18,240 B

__device__ __forceinline__ unsigned smem_u32(const void* p) {
    return (unsigned)__cvta_generic_to_shared(p);
}

__device__ __forceinline__ void ldsm_x4(unsigned& r0, unsigned& r1,
                                        unsigned& r2, unsigned& r3, unsigned addr) {
    asm volatile("ldmatrix.sync.aligned.m8n8.x4.shared.b16 {%0,%1,%2,%3}, [%4];"
                 : "=r"(r0), "=r"(r1), "=r"(r2), "=r"(r3) : "r"(addr));
}

__device__ __forceinline__ void mma_tf32(float c[4],
                                         unsigned a0, unsigned a1, unsigned a2, unsigned a3,
                                         unsigned b0, unsigned b1) {
    asm volatile("mma.sync.aligned.m16n8k8.row.col.f32.tf32.tf32.f32 "
                 "{%0,%1,%2,%3}, {%4,%5,%6,%7}, {%8,%9}, {%0,%1,%2,%3};"
                 : "+f"(c[0]), "+f"(c[1]), "+f"(c[2]), "+f"(c[3])
                 : "r"(a0), "r"(a1), "r"(a2), "r"(a3), "r"(b0), "r"(b1));
}

__device__ __forceinline__ unsigned tf32_hi(unsigned x) {
    unsigned r;
    asm("cvt.rna.tf32.f32 %0, %1;" : "=r"(r) : "r"(x));
    return r;
}
__device__ __forceinline__ unsigned fu(float x) { return __float_as_uint(x); }
__device__ __forceinline__ float rna_f(float x) {
    return __uint_as_float(tf32_hi(__float_as_uint(x)));
}

// ---------------------------------------------------------------------------
// Prepass: pack K and V into fragment-native, tf32-pre-rounded float2 tiles.
// ---------------------------------------------------------------------------
__global__ void __launch_bounds__(128)
pack_kv_kernel(const float* __restrict__ k, const float* __restrict__ v)
{
    const int nb = blockIdx.x, h = blockIdx.y;
    const float* kb = k + ((size_t)nb * BS_ * HH_ + h) * DD_;
    const float* vb = v + ((size_t)nb * BS_ * HH_ + h) * DD_;
    float2* kout = g_kpack + ((size_t)h * NB_ + nb) * 4096;
    float2* vout = g_vpack + ((size_t)h * NB_ + nb) * 4096;

    // K: pos = ((ub*16 + kt)*4 + p)*8 + ul
    for (int pos = threadIdx.x; pos < 4096; pos += 128) {
        int ul = pos & 7, p = (pos >> 3) & 3, kt = (pos >> 5) & 15, ub = pos >> 9;
        int u = ub * 8 + ul, d = kt * 8 + p;
        kout[pos] = make_float2(rna_f(kb[(size_t)u * (HH_ * DD_) + d]),
                                rna_f(kb[(size_t)u * (HH_ * DD_) + d + 4]));
    }
    // V: pos = ((db*8 + kt)*4 + p)*8 + dl
    for (int pos = threadIdx.x; pos < 4096; pos += 128) {
        int dl = pos & 7, p = (pos >> 3) & 3, kt = (pos >> 5) & 7, db = pos >> 8;
        int d = db * 8 + dl, u = kt * 8 + p;
        vout[pos] = make_float2(rna_f(vb[(size_t)u * (HH_ * DD_) + d]),
                                rna_f(vb[(size_t)(u + 4) * (HH_ * DD_) + d]));
    }
}

// ---------------------------------------------------------------------------
// Main kernel
// ---------------------------------------------------------------------------
__global__ void __launch_bounds__(128, 5)
hsa_prefill_kernel(const float* __restrict__ q, const float* __restrict__ w,
                   const int* __restrict__ bi, float* __restrict__ out)
{
    extern __shared__ float sm[];
    const int lq   = blockIdx.x;
    const int h    = blockIdx.y;
    const int tid  = threadIdx.x;
    const int warp = tid >> 5;
    const int lane = tid & 31;
    const int gID  = lane >> 2;   // 0..7
    const int tig  = lane & 3;    // 0..3

    // ---- Load Q tile [16][128]; store rna(Q * SM_SCALE).
    {
        const float* qb = q + ((size_t)lq * HQ_ + (size_t)h * GG_) * DD_;
        #pragma unroll
        for (int i = tid; i < (GG_ * DD_) / 4; i += 128) {
            int idx = i * 4;
            int g = idx >> 7, d = idx & 127;
            float4 val = *(const float4*)(qb + idx);
            *(uint4*)(sm + QSH_OFF + g * QS_STR + d) =
                make_uint4(tf32_hi(fu(val.x * SM_SCALE)),
                           tf32_hi(fu(val.y * SM_SCALE)),
                           tf32_hi(fu(val.z * SM_SCALE)),
                           tf32_hi(fu(val.w * SM_SCALE)));
        }
        const float* wb = w + ((size_t)lq * HQ_ + (size_t)h * GG_) * SS_;
        for (int i = tid; i < GG_ * SS_; i += 128) sm[WS_OFF + i] = wb[i];
        if (tid < SS_)
            ((int*)(sm + IDX_OFF))[tid] = bi[((size_t)lq * HH_ + h) * SS_ + tid];
    }
    __syncthreads();

    // Persistent O accumulators
    float oh[4][4];
    #pragma unroll
    for (int i = 0; i < 4; i++)
        #pragma unroll
        for (int j = 0; j < 4; j++) oh[i][j] = 0.f;

    // ldmatrix A-fragment address components
    const int lr = lane & 7;
    const int lt = lane >> 3;
    const int a_row = lr + ((lt & 1) << 3);
    const int a_col = (lt >> 1) << 2;

    // Per-lane packed-tile offsets (float2 units)
    const int lane_off = tig * 8 + gID;
    const float2* kp_base = g_kpack + (size_t)h * NB_ * 4096
                          + (warp * 2) * 512 + lane_off;
    const float2* vp_base = g_vpack + (size_t)h * NB_ * 4096
                          + (warp * 4) * 256 + lane_off;

    for (int s = 0; s < SS_; s++) {
        const int blk = ((const int*)(sm + IDX_OFF))[s];   // uniform across CTA
        float* psh = sm + PSH_OFF + (s & 1) * (16 * PS_STR);

        if (blk >= 0) {
            const float2* kp = kp_base + (size_t)blk * 4096;

            // ---- Scores S[16][64] = rna(Q*scale) @ K̃^T
            float cm[2][4] = {{0.f,0.f,0.f,0.f},{0.f,0.f,0.f,0.f}};
            #pragma unroll
            for (int kt = 0; kt < 16; kt++) {
                unsigned a0, a1, a2, a3;
                ldsm_x4(a0, a1, a2, a3,
                        smem_u32(sm + QSH_OFF + a_row * QS_STR + a_col + kt * 8));
                float2 k0 = kp[kt * 32];          // n-tile u0 = warp*16
                float2 k1 = kp[512 + kt * 32];    // n-tile u0 = warp*16 + 8
                mma_tf32(cm[0], a0, a1, a2, a3, fu(k0.x), fu(k0.y));
                mma_tf32(cm[1], a0, a1, a2, a3, fu(k1.x), fu(k1.y));
            }
            // Spill scores (already scaled via Q) into PSH scratch
            #pragma unroll
            for (int nt = 0; nt < 2; nt++) {
                const int u = (warp * 2 + nt) * 8 + tig * 2;
                *(float2*)(psh + gID * PS_STR + u) =
                    make_float2(cm[nt][0], cm[nt][1]);
                *(float2*)(psh + (gID + 8) * PS_STR + u) =
                    make_float2(cm[nt][2], cm[nt][3]);
            }
            __syncthreads();

            // ---- Softmax over 64 keys; fold w[g][s]/sum; write rna(P).
            {
                const int g = tid >> 3, j = tid & 7;
                float vals[8];
                #pragma unroll
                for (int m = 0; m < 8; m++) vals[m] = psh[g * PS_STR + j + m * 8];
                float mx = vals[0];
                #pragma unroll
                for (int m = 1; m < 8; m++) mx = fmaxf(mx, vals[m]);
                mx = fmaxf(mx, __shfl_xor_sync(0xffffffffu, mx, 1));
                mx = fmaxf(mx, __shfl_xor_sync(0xffffffffu, mx, 2));
                mx = fmaxf(mx, __shfl_xor_sync(0xffffffffu, mx, 4));
                float sum = 0.f;
                #pragma unroll
                for (int m = 0; m < 8; m++) { vals[m] = __expf(vals[m] - mx); sum += vals[m]; }
                sum += __shfl_xor_sync(0xffffffffu, sum, 1);
                sum += __shfl_xor_sync(0xffffffffu, sum, 2);
                sum += __shfl_xor_sync(0xffffffffu, sum, 4);
                const float coef = sm[WS_OFF + g * SS_ + s] / sum;
                #pragma unroll
                for (int m = 0; m < 8; m++)
                    psh[g * PS_STR + j + m * 8] = rna_f(vals[m] * coef);
            }
            __syncthreads();

            // ---- O[16][128] += rna(P) @ Ṽ   (V via 4 independent LDG.64/kt)
            const float2* vp = vp_base + (size_t)blk * 4096;
            #pragma unroll
            for (int kt = 0; kt < 8; kt++) {
                unsigned a0, a1, a2, a3;
                ldsm_x4(a0, a1, a2, a3,
                        smem_u32(psh + a_row * PS_STR + a_col + kt * 8));
                #pragma unroll
                for (int nt = 0; nt < 4; nt++) {
                    float2 vv = vp[nt * 256 + kt * 32];
                    mma_tf32(oh[nt], a0, a1, a2, a3, fu(vv.x), fu(vv.y));
                }
            }
            // No end barrier: next iteration uses the OTHER P buffer.
        }
    }

    // ---- Write O: warp's d-slice, fragment rows gID / gID+8.
    float* ob = out + ((size_t)lq * HQ_ + (size_t)h * GG_) * DD_;
    #pragma unroll
    for (int nt = 0; nt < 4; nt++) {
        const int d = warp * 32 + nt * 8 + tig * 2;
        *(float2*)(ob + (size_t)gID * DD_ + d)       = make_float2(oh[nt][0], oh[nt][1]);
        *(float2*)(ob + (size_t)(gID + 8) * DD_ + d) = make_float2(oh[nt][2], oh[nt][3]);
    }
}

extern "C" void kernel_launch(void* const* d_in, const int* in_sizes, int n_in,
                              void* d_out, int out_size)
{
    const float* q  = (const float*)d_in[0];
    const float* k  = (const float*)d_in[1];
    const float* v  = (const float*)d_in[2];
    const float* w  = (const float*)d_in[3];
    const int*   bi = (const int*)d_in[4];
    float* out = (float*)d_out;

    pack_kv_kernel<<<dim3(NB_, HH_), 128>>>(k, v);

    cudaFuncSetAttribute(hsa_prefill_kernel,
                         cudaFuncAttributeMaxDynamicSharedMemorySize, SMEM_BYTES);
    hsa_prefill_kernel<<<dim3(LQ_, HH_), 128, SMEM_BYTES>>>(q, w, bi, out);
}